// round 1
// baseline (speedup 1.0000x reference)
#include <cuda_runtime.h>
#include <math.h>

// AttentionBlock: out = smooth_softmax((x@Wq)@(y@Wk)^T / 16) @ (y@Wv)
// smooth_softmax(s) = (0.1*relu(s) + softmax(s)) / (0.1*sum(relu(s)) + 1)
// Decomposition (no online max needed; scores ~N(0,1)):
//   out_row = (accE/Z + 0.1*accR) / (0.1*R + 1)
//   accE = sum_j exp(s_j) v_j, accR = sum_j relu(s_j) v_j, Z = sum exp, R = sum relu

#define N_Q   16384
#define MCTX  4096
#define S_IN  256
#define D_P   256

#define QT    32
#define KT    64
#define ATT_THREADS 256
#define QSTR  260   // Qs row stride (pad: 4-row groups hit distinct banks)

// scratch (device globals: allocation-free)
__device__ float g_Q [N_Q * D_P];     // 16 MB
__device__ float g_KT[D_P * MCTX];    // 4 MB, [d][m] (transposed)
__device__ float g_V [MCTX * D_P];    // 4 MB, [m][d]

// ---------------------------------------------------------------------------
// K / V projection: y [4096,7] @ Wk|Wv [7,256]. K stored transposed.
// ---------------------------------------------------------------------------
__global__ __launch_bounds__(256) void proj_kv_kernel(const float* __restrict__ y,
                                                      const float* __restrict__ Wk,
                                                      const float* __restrict__ Wv) {
    int idx = blockIdx.x * blockDim.x + threadIdx.x;
    const int total = MCTX * D_P;
    if (idx < total) {
        // K part: m fastest -> coalesced store into g_KT[p][m]
        int m = idx & (MCTX - 1);
        int p = idx >> 12;
        float a = 0.f;
        #pragma unroll
        for (int j = 0; j < 7; j++)
            a = fmaf(y[m * 7 + j], Wk[j * D_P + p], a);
        g_KT[p * MCTX + m] = a;
    } else if (idx < 2 * total) {
        // V part: p fastest -> coalesced store into g_V[m][p]
        int i2 = idx - total;
        int m = i2 >> 8;
        int p = i2 & (D_P - 1);
        float a = 0.f;
        #pragma unroll
        for (int j = 0; j < 7; j++)
            a = fmaf(y[m * 7 + j], Wv[j * D_P + p], a);
        g_V[m * D_P + p] = a;
    }
}

// ---------------------------------------------------------------------------
// Q GEMM: g_Q [16384,256] = x [16384,256] @ Wq [256,256]
// 64x64 tile, BK=16, 256 threads, 4x4 micro-tile.
// ---------------------------------------------------------------------------
__global__ __launch_bounds__(256) void qgemm_kernel(const float* __restrict__ A,
                                                    const float* __restrict__ B) {
    __shared__ float As[16][68];
    __shared__ float Bs[16][68];
    int m0 = blockIdx.y * 64;
    int n0 = blockIdx.x * 64;
    int t  = threadIdx.x;
    int tm = t >> 4;
    int tn = t & 15;
    float acc[4][4] = {};
    for (int k0 = 0; k0 < S_IN; k0 += 16) {
        {
            int ar = t >> 2;
            int ak = (t & 3) << 2;
            float4 av = *(const float4*)&A[(m0 + ar) * S_IN + k0 + ak];
            As[ak + 0][ar] = av.x; As[ak + 1][ar] = av.y;
            As[ak + 2][ar] = av.z; As[ak + 3][ar] = av.w;
        }
        {
            int br = t >> 4;
            int bn = (t & 15) << 2;
            *(float4*)&Bs[br][bn] = *(const float4*)&B[(k0 + br) * D_P + n0 + bn];
        }
        __syncthreads();
        #pragma unroll
        for (int k = 0; k < 16; k++) {
            float4 a4 = *(const float4*)&As[k][tm << 2];
            float4 b4 = *(const float4*)&Bs[k][tn << 2];
            float av_[4] = {a4.x, a4.y, a4.z, a4.w};
            float bv_[4] = {b4.x, b4.y, b4.z, b4.w};
            #pragma unroll
            for (int i = 0; i < 4; i++)
                #pragma unroll
                for (int j = 0; j < 4; j++)
                    acc[i][j] = fmaf(av_[i], bv_[j], acc[i][j]);
        }
        __syncthreads();
    }
    #pragma unroll
    for (int i = 0; i < 4; i++) {
        float4 o = make_float4(acc[i][0], acc[i][1], acc[i][2], acc[i][3]);
        *(float4*)&g_Q[(m0 + (tm << 2) + i) * D_P + n0 + (tn << 2)] = o;
    }
}

// ---------------------------------------------------------------------------
// Fused attention: each CTA handles QT=32 queries, streams K/V in KT=64 tiles.
// ---------------------------------------------------------------------------
__global__ __launch_bounds__(ATT_THREADS) void attn_kernel(float* __restrict__ out) {
    extern __shared__ float sm[];
    float* Qs   = sm;                       // QT * QSTR
    float* KsT  = Qs  + QT * QSTR;          // D_P * KT  ([d][k])
    float* Vs   = KsT + D_P * KT;           // KT * D_P  ([k][d])
    float* Es   = Vs  + KT * D_P;           // QT * KT
    float* Rs   = Es  + QT * KT;            // QT * KT
    float* Zacc = Rs  + QT * KT;            // QT
    float* Racc = Zacc + QT;                // QT

    const int t  = threadIdx.x;
    const int q0 = blockIdx.x * QT;

    // Load Q tile (32 x 256)
    #pragma unroll
    for (int i = 0; i < 8; i++) {
        int fid = t + i * ATT_THREADS;      // float4 id over 32*64
        int q  = fid >> 6;
        int dq = (fid & 63) << 2;
        float4 v = *(const float4*)&g_Q[(q0 + q) * D_P + dq];
        *(float4*)&Qs[q * QSTR + dq] = v;
    }
    if (t < QT) { Zacc[t] = 0.f; Racc[t] = 0.f; }

    const int qg = t >> 4;       // 0..15 : queries 2qg, 2qg+1 (score phase)
    const int kg = t & 15;       // keys 4kg..4kg+3
    const int dg = t & 31;       // PV phase: dims dg*8 .. dg*8+7
    const int qbase = (t >> 5) << 2;  // PV phase: queries qbase..qbase+3

    float accE[4][8];
    float accR[4][8];
    #pragma unroll
    for (int i = 0; i < 4; i++)
        #pragma unroll
        for (int j = 0; j < 8; j++) { accE[i][j] = 0.f; accR[i][j] = 0.f; }

    for (int k0 = 0; k0 < MCTX; k0 += KT) {
        __syncthreads();   // prev PV done (and Q/Zacc init on first iter)

        // Load K tile transposed: KsT[d][k] <- g_KT[d][k0+k]
        #pragma unroll
        for (int i = 0; i < 16; i++) {
            int fid = t + i * ATT_THREADS;  // float4 over 256*16
            int d  = fid >> 4;
            int kq = (fid & 15) << 2;
            float4 v = *(const float4*)&g_KT[d * MCTX + k0 + kq];
            *(float4*)&KsT[d * KT + kq] = v;
        }
        // Load V tile: Vs[k][d]
        #pragma unroll
        for (int i = 0; i < 16; i++) {
            int fid = t + i * ATT_THREADS;  // float4 over 64*64
            int k  = fid >> 6;
            int dq = (fid & 63) << 2;
            float4 v = *(const float4*)&g_V[(k0 + k) * D_P + dq];
            *(float4*)&Vs[k * D_P + dq] = v;
        }
        __syncthreads();

        // ---- score phase: 2 queries x 4 keys per thread, K=256 dot ----
        float s0[4] = {0.f, 0.f, 0.f, 0.f};
        float s1[4] = {0.f, 0.f, 0.f, 0.f};
        const float* qrow0 = &Qs[(2 * qg) * QSTR];
        const float* qrow1 = qrow0 + QSTR;
        const int kcol = kg << 2;
        #pragma unroll 4
        for (int d = 0; d < D_P; d += 4) {
            float4 ka = *(const float4*)&KsT[(d + 0) * KT + kcol];
            float4 kb = *(const float4*)&KsT[(d + 1) * KT + kcol];
            float4 kc = *(const float4*)&KsT[(d + 2) * KT + kcol];
            float4 kd = *(const float4*)&KsT[(d + 3) * KT + kcol];
            float4 qa = *(const float4*)&qrow0[d];
            float4 qb = *(const float4*)&qrow1[d];
            #define SFMA(S, qv, K)                      \
                S[0] = fmaf(qv, K.x, S[0]);             \
                S[1] = fmaf(qv, K.y, S[1]);             \
                S[2] = fmaf(qv, K.z, S[2]);             \
                S[3] = fmaf(qv, K.w, S[3]);
            SFMA(s0, qa.x, ka) SFMA(s0, qa.y, kb) SFMA(s0, qa.z, kc) SFMA(s0, qa.w, kd)
            SFMA(s1, qb.x, ka) SFMA(s1, qb.y, kb) SFMA(s1, qb.z, kc) SFMA(s1, qb.w, kd)
            #undef SFMA
        }

        // ---- convert: weights + row stats ----
        {
            const float scale = 0.0625f;   // 1/sqrt(256)
            float z0 = 0.f, z1 = 0.f, r0 = 0.f, r1 = 0.f;
            #pragma unroll
            for (int j = 0; j < 4; j++) {
                float sv0 = s0[j] * scale;
                float sv1 = s1[j] * scale;
                float e0 = __expf(sv0);
                float e1 = __expf(sv1);
                float rr0 = fmaxf(sv0, 0.f);
                float rr1 = fmaxf(sv1, 0.f);
                Es[(2 * qg + 0) * KT + kcol + j] = e0;
                Es[(2 * qg + 1) * KT + kcol + j] = e1;
                Rs[(2 * qg + 0) * KT + kcol + j] = rr0;
                Rs[(2 * qg + 1) * KT + kcol + j] = rr1;
                z0 += e0; z1 += e1; r0 += rr0; r1 += rr1;
            }
            #pragma unroll
            for (int off = 8; off > 0; off >>= 1) {
                z0 += __shfl_down_sync(0xffffffffu, z0, off, 16);
                z1 += __shfl_down_sync(0xffffffffu, z1, off, 16);
                r0 += __shfl_down_sync(0xffffffffu, r0, off, 16);
                r1 += __shfl_down_sync(0xffffffffu, r1, off, 16);
            }
            if (kg == 0) {
                Zacc[2 * qg + 0] += z0;
                Zacc[2 * qg + 1] += z1;
                Racc[2 * qg + 0] += r0;
                Racc[2 * qg + 1] += r1;
            }
        }
        __syncthreads();

        // ---- PV phase: 4 queries x 8 dims per thread, both accumulators ----
        #pragma unroll 2
        for (int k = 0; k < KT; k++) {
            float4 v0 = *(const float4*)&Vs[k * D_P + (dg << 3)];
            float4 v1 = *(const float4*)&Vs[k * D_P + (dg << 3) + 4];
            #pragma unroll
            for (int qi = 0; qi < 4; qi++) {
                float e = Es[(qbase + qi) * KT + k];
                float r = Rs[(qbase + qi) * KT + k];
                accE[qi][0] = fmaf(e, v0.x, accE[qi][0]);
                accE[qi][1] = fmaf(e, v0.y, accE[qi][1]);
                accE[qi][2] = fmaf(e, v0.z, accE[qi][2]);
                accE[qi][3] = fmaf(e, v0.w, accE[qi][3]);
                accE[qi][4] = fmaf(e, v1.x, accE[qi][4]);
                accE[qi][5] = fmaf(e, v1.y, accE[qi][5]);
                accE[qi][6] = fmaf(e, v1.z, accE[qi][6]);
                accE[qi][7] = fmaf(e, v1.w, accE[qi][7]);
                accR[qi][0] = fmaf(r, v0.x, accR[qi][0]);
                accR[qi][1] = fmaf(r, v0.y, accR[qi][1]);
                accR[qi][2] = fmaf(r, v0.z, accR[qi][2]);
                accR[qi][3] = fmaf(r, v0.w, accR[qi][3]);
                accR[qi][4] = fmaf(r, v1.x, accR[qi][4]);
                accR[qi][5] = fmaf(r, v1.y, accR[qi][5]);
                accR[qi][6] = fmaf(r, v1.z, accR[qi][6]);
                accR[qi][7] = fmaf(r, v1.w, accR[qi][7]);
            }
        }
    }
    __syncthreads();

    // ---- epilogue ----
    #pragma unroll
    for (int qi = 0; qi < 4; qi++) {
        int q = qbase + qi;
        float iz = 1.f / Zacc[q];
        float dn = 1.f / fmaf(0.1f, Racc[q], 1.f);
        float o[8];
        #pragma unroll
        for (int j = 0; j < 8; j++)
            o[j] = (accE[qi][j] * iz + 0.1f * accR[qi][j]) * dn;
        float4 o0 = make_float4(o[0], o[1], o[2], o[3]);
        float4 o1 = make_float4(o[4], o[5], o[6], o[7]);
        *(float4*)&out[(q0 + q) * D_P + (dg << 3)]     = o0;
        *(float4*)&out[(q0 + q) * D_P + (dg << 3) + 4] = o1;
    }
}

// ---------------------------------------------------------------------------

static const int ATT_SMEM_BYTES =
    (QT * QSTR + D_P * KT + KT * D_P + 2 * QT * KT + 2 * QT) * (int)sizeof(float);

extern "C" void kernel_launch(void* const* d_in, const int* in_sizes, int n_in,
                              void* d_out, int out_size) {
    const float* x  = (const float*)d_in[0];
    const float* y  = (const float*)d_in[1];
    const float* Wq = (const float*)d_in[2];
    const float* Wk = (const float*)d_in[3];
    const float* Wv = (const float*)d_in[4];
    float* out = (float*)d_out;

    cudaFuncSetAttribute(attn_kernel, cudaFuncAttributeMaxDynamicSharedMemorySize,
                         ATT_SMEM_BYTES);

    proj_kv_kernel<<<(2 * MCTX * D_P + 255) / 256, 256>>>(y, Wk, Wv);
    qgemm_kernel<<<dim3(D_P / 64, N_Q / 64), 256>>>(x, Wq);
    attn_kernel<<<N_Q / QT, ATT_THREADS, ATT_SMEM_BYTES>>>(out);
}

// round 5
// speedup vs baseline: 4.0260x; 4.0260x over previous
#include <cuda_runtime.h>
#include <cstdint>
#include <math.h>

// AttentionBlock via mma.sync m16n8k8 tf32 (base-PTX, runs on sm_103 HMMA path).
// out = smooth_softmax((x@Wq)@(y@Wk)^T / 16) @ (y@Wv)
// Per row: out = (accE/Z + 0.1*accR) / (0.1*R + 1)

#define N_Q   16384
#define MCTX  4096
#define S_IN  256
#define D_P   256
#define KT    32                 // keys per tile
#define NT    (MCTX / KT)        // 128 tiles
#define DH    128                // output dims per CTA

// scratch (fragment-packed layouts)
__device__ float  g_Q  [N_Q * D_P];          // qgemm output, row-major, tf32-rounded
__device__ float4 g_Qf [N_Q * D_P / 4];      // [qblk][w8][s32][lane32] -> {a0,a1,a2,a3}
__device__ float  g_Kf [MCTX * D_P];         // [tile][s32][nt4][lane32][2] -> {b0,b1}
__device__ float  g_Vf [MCTX * D_P];         // [tile][h2][sp4][nt16][lane32][2]

// ---------------------------------------------------------------- helpers
__device__ __forceinline__ uint32_t smem_u32(const void* p) {
    uint32_t a;
    asm("{ .reg .u64 t; cvta.to.shared.u64 t, %1; cvt.u32.u64 %0, t; }" : "=r"(a) : "l"(p));
    return a;
}
__device__ __forceinline__ uint32_t f2tf32(float x) {
    uint32_t r; asm("cvt.rna.tf32.f32 %0, %1;" : "=r"(r) : "f"(x)); return r;
}
__device__ __forceinline__ void lds128(uint32_t r[4], uint32_t a) {
    asm volatile("ld.shared.v4.b32 {%0,%1,%2,%3}, [%4];"
        : "=r"(r[0]), "=r"(r[1]), "=r"(r[2]), "=r"(r[3]) : "r"(a));
}
__device__ __forceinline__ void lds64(uint32_t r[2], uint32_t a) {
    asm volatile("ld.shared.v2.b32 {%0,%1}, [%2];" : "=r"(r[0]), "=r"(r[1]) : "r"(a));
}
__device__ __forceinline__ void mma_tf32(float c[4], const uint32_t a[4], const uint32_t b[2]) {
    asm volatile("mma.sync.aligned.m16n8k8.row.col.f32.tf32.tf32.f32 "
        "{%0,%1,%2,%3}, {%4,%5,%6,%7}, {%8,%9}, {%0,%1,%2,%3};"
        : "+f"(c[0]), "+f"(c[1]), "+f"(c[2]), "+f"(c[3])
        : "r"(a[0]), "r"(a[1]), "r"(a[2]), "r"(a[3]), "r"(b[0]), "r"(b[1]));
}
#define CP16(dst, src) \
    asm volatile("cp.async.cg.shared.global [%0], [%1], 16;" :: "r"(dst), "l"(src))
#define CP_COMMIT() asm volatile("cp.async.commit_group;" ::: "memory")

// ---------------------------------------------------------------- K/V projection
// writes fragment-packed g_Kf / g_Vf directly (coalesced stores).
__global__ __launch_bounds__(256) void proj_kv_kernel(const float* __restrict__ y,
                                                      const float* __restrict__ Wk,
                                                      const float* __restrict__ Wv) {
    int a = blockIdx.x * blockDim.x + threadIdx.x;
    const int total = MCTX * D_P;   // 1M
    if (a < total) {
        // K frag: b=a&1, lane=(a>>1)&31, nt=(a>>6)&3, s=(a>>8)&31, tile=a>>13
        int b = a & 1, lane = (a >> 1) & 31, nt = (a >> 6) & 3, s = (a >> 8) & 31, tile = a >> 13;
        int m = tile * KT + nt * 8 + (lane >> 2);
        int p = s * 8 + (lane & 3) + 4 * b;
        float acc = 0.f;
        #pragma unroll
        for (int j = 0; j < 7; j++) acc = fmaf(y[m * 7 + j], Wk[j * D_P + p], acc);
        g_Kf[a] = __uint_as_float(f2tf32(acc));
    } else if (a < 2 * total) {
        int a2 = a - total;
        // V frag: b, lane, nt(16), sp(4), h(2), tile
        int b = a2 & 1, lane = (a2 >> 1) & 31, nt = (a2 >> 6) & 15;
        int sp = (a2 >> 10) & 3, h = (a2 >> 12) & 1, tile = a2 >> 13;
        int m = tile * KT + sp * 8 + (lane & 3) + 4 * b;
        int d = h * DH + nt * 8 + (lane >> 2);
        float acc = 0.f;
        #pragma unroll
        for (int j = 0; j < 7; j++) acc = fmaf(y[m * 7 + j], Wv[j * D_P + d], acc);
        g_Vf[a2] = __uint_as_float(f2tf32(acc));
    }
}

// ---------------------------------------------------------------- Q GEMM (fp32 SIMT)
__global__ __launch_bounds__(256) void qgemm_kernel(const float* __restrict__ A,
                                                    const float* __restrict__ B) {
    __shared__ float As[16][68];
    __shared__ float Bs[16][68];
    int m0 = blockIdx.y * 64, n0 = blockIdx.x * 64;
    int t = threadIdx.x, tm = t >> 4, tn = t & 15;
    float acc[4][4] = {};
    for (int k0 = 0; k0 < S_IN; k0 += 16) {
        {
            int ar = t >> 2, ak = (t & 3) << 2;
            float4 av = *(const float4*)&A[(m0 + ar) * S_IN + k0 + ak];
            As[ak + 0][ar] = av.x; As[ak + 1][ar] = av.y;
            As[ak + 2][ar] = av.z; As[ak + 3][ar] = av.w;
        }
        {
            int br = t >> 4, bn = (t & 15) << 2;
            *(float4*)&Bs[br][bn] = *(const float4*)&B[(k0 + br) * D_P + n0 + bn];
        }
        __syncthreads();
        #pragma unroll
        for (int k = 0; k < 16; k++) {
            float4 a4 = *(const float4*)&As[k][tm << 2];
            float4 b4 = *(const float4*)&Bs[k][tn << 2];
            float av_[4] = {a4.x, a4.y, a4.z, a4.w};
            float bv_[4] = {b4.x, b4.y, b4.z, b4.w};
            #pragma unroll
            for (int i = 0; i < 4; i++)
                #pragma unroll
                for (int j = 0; j < 4; j++)
                    acc[i][j] = fmaf(av_[i], bv_[j], acc[i][j]);
        }
        __syncthreads();
    }
    #pragma unroll
    for (int i = 0; i < 4; i++) {
        float4 o = make_float4(__uint_as_float(f2tf32(acc[i][0])),
                               __uint_as_float(f2tf32(acc[i][1])),
                               __uint_as_float(f2tf32(acc[i][2])),
                               __uint_as_float(f2tf32(acc[i][3])));
        *(float4*)&g_Q[(size_t)(m0 + (tm << 2) + i) * D_P + n0 + (tn << 2)] = o;
    }
}

// ---------------------------------------------------------------- Q repack (row-major -> A frags)
__global__ __launch_bounds__(256) void qrepack_kernel() {
    int u = blockIdx.x * 256 + threadIdx.x;       // one float4 per thread, 1M total
    int lane = u & 31, s = (u >> 5) & 31, w = (u >> 10) & 7, qb = u >> 13;
    int r = qb * 128 + w * 16 + (lane >> 2);
    int c = s * 8 + (lane & 3);
    float4 v = make_float4(g_Q[(size_t)r * D_P + c],
                           g_Q[(size_t)(r + 8) * D_P + c],
                           g_Q[(size_t)r * D_P + c + 4],
                           g_Q[(size_t)(r + 8) * D_P + c + 4]);
    g_Qf[u] = v;
}

// ---------------------------------------------------------------- fused attention
// SMEM: Qf 128K | Kf 2x32K | Vf 2x16K = 224K
#define QS_BYTES  131072
#define KS_BYTES  32768
#define VS_BYTES  16384
#define ATT_SMEM  (QS_BYTES + 2 * KS_BYTES + 2 * VS_BYTES)

__global__ __launch_bounds__(256, 1) void attn_kernel(float* __restrict__ out) {
    extern __shared__ char smem[];
    const uint32_t sb = smem_u32(smem);
    const uint32_t QS = sb, KS = sb + QS_BYTES, VS = KS + 2 * KS_BYTES;

    const int t    = threadIdx.x;
    const int w    = t >> 5;
    const int lane = t & 31;
    const int g    = lane >> 2;
    const int q    = lane & 3;
    const int qblk = blockIdx.x;
    const int h    = blockIdx.y;
    const int q0   = qblk * 128;
    const int dh0  = h * DH;

    // ---- prologue: Q + tile0 K/V ----
    {
        const float* qsrc = (const float*)(g_Qf + (size_t)qblk * 8192);
        #pragma unroll
        for (int i = 0; i < 32; i++) {
            int f = t + (i << 8);
            CP16(QS + f * 16, qsrc + f * 4);
        }
        const float* ksrc = g_Kf;
        #pragma unroll
        for (int i = 0; i < 8; i++) {
            int f = t + (i << 8);
            CP16(KS + f * 16, ksrc + f * 4);
        }
        const float* vsrc = g_Vf + (size_t)h * 4096;
        #pragma unroll
        for (int i = 0; i < 4; i++) {
            int f = t + (i << 8);
            CP16(VS + f * 16, vsrc + f * 4);
        }
        CP_COMMIT();
    }

    float accE[16][4], accR[16][4];
    #pragma unroll
    for (int n = 0; n < 16; n++)
        #pragma unroll
        for (int i = 0; i < 4; i++) { accE[n][i] = 0.f; accR[n][i] = 0.f; }
    float zg = 0.f, zg8 = 0.f, rg = 0.f, rg8 = 0.f;

    const int srcq = (lane & ~3) + (q >> 1);
    const int srcq2 = srcq + 2;
    const int qodd = q & 1;

    for (int tile = 0; tile < NT; tile++) {
        // prefetch next K/V
        if (tile + 1 < NT) {
            uint32_t KSn = KS + ((tile + 1) & 1) * KS_BYTES;
            uint32_t VSn = VS + ((tile + 1) & 1) * VS_BYTES;
            const float* ksrc = g_Kf + (size_t)(tile + 1) * 8192;
            const float* vsrc = g_Vf + ((size_t)(tile + 1) * 2 + h) * 4096;
            #pragma unroll
            for (int i = 0; i < 8; i++) {
                int f = t + (i << 8);
                CP16(KSn + f * 16, ksrc + f * 4);
            }
            #pragma unroll
            for (int i = 0; i < 4; i++) {
                int f = t + (i << 8);
                CP16(VSn + f * 16, vsrc + f * 4);
            }
            CP_COMMIT();
            asm volatile("cp.async.wait_group 1;" ::: "memory");
        } else {
            asm volatile("cp.async.wait_group 0;" ::: "memory");
        }
        __syncthreads();

        const uint32_t KSb = KS + (tile & 1) * KS_BYTES;
        const uint32_t VSb = VS + (tile & 1) * VS_BYTES;

        // ---- S = Q @ K^T : 16q x 32keys per warp ----
        float sc[4][4];
        #pragma unroll
        for (int n = 0; n < 4; n++)
            #pragma unroll
            for (int i = 0; i < 4; i++) sc[n][i] = 0.f;

        #pragma unroll 8
        for (int s = 0; s < 32; s++) {
            uint32_t a[4];
            lds128(a, QS + (uint32_t)(w * 1024 + s * 32 + lane) * 16);
            #pragma unroll
            for (int nt = 0; nt < 4; nt++) {
                uint32_t b[2];
                lds64(b, KSb + (uint32_t)(s * 256 + nt * 64 + lane * 2) * 4);
                mma_tf32(sc[nt], a, b);
            }
        }

        // ---- per 8-key group: weights, row sums, PV mma ----
        #pragma unroll
        for (int sp = 0; sp < 4; sp++) {
            uint32_t ef[4], rf[4];
            #pragma unroll
            for (int i = 0; i < 4; i++) {
                float sv = sc[sp][i] * 0.0625f;
                float e  = __expf(sv);
                float rv = fmaxf(sv, 0.f);
                ef[i] = f2tf32(e);
                rf[i] = f2tf32(rv);
                float ev = __uint_as_float(ef[i]);
                float rr = __uint_as_float(rf[i]);
                if (i < 2) { zg += ev; rg += rr; } else { zg8 += ev; rg8 += rr; }
            }
            // C-layout -> A-layout permute (quad shuffles)
            uint32_t aE[4], aR[4];
            {
                uint32_t x0 = __shfl_sync(0xffffffffu, ef[0], srcq);
                uint32_t x1 = __shfl_sync(0xffffffffu, ef[1], srcq);
                aE[0] = qodd ? x1 : x0;
                uint32_t x2 = __shfl_sync(0xffffffffu, ef[2], srcq);
                uint32_t x3 = __shfl_sync(0xffffffffu, ef[3], srcq);
                aE[1] = qodd ? x3 : x2;
                uint32_t y0 = __shfl_sync(0xffffffffu, ef[0], srcq2);
                uint32_t y1 = __shfl_sync(0xffffffffu, ef[1], srcq2);
                aE[2] = qodd ? y1 : y0;
                uint32_t y2 = __shfl_sync(0xffffffffu, ef[2], srcq2);
                uint32_t y3 = __shfl_sync(0xffffffffu, ef[3], srcq2);
                aE[3] = qodd ? y3 : y2;
            }
            {
                uint32_t x0 = __shfl_sync(0xffffffffu, rf[0], srcq);
                uint32_t x1 = __shfl_sync(0xffffffffu, rf[1], srcq);
                aR[0] = qodd ? x1 : x0;
                uint32_t x2 = __shfl_sync(0xffffffffu, rf[2], srcq);
                uint32_t x3 = __shfl_sync(0xffffffffu, rf[3], srcq);
                aR[1] = qodd ? x3 : x2;
                uint32_t y0 = __shfl_sync(0xffffffffu, rf[0], srcq2);
                uint32_t y1 = __shfl_sync(0xffffffffu, rf[1], srcq2);
                aR[2] = qodd ? y1 : y0;
                uint32_t y2 = __shfl_sync(0xffffffffu, rf[2], srcq2);
                uint32_t y3 = __shfl_sync(0xffffffffu, rf[3], srcq2);
                aR[3] = qodd ? y3 : y2;
            }
            #pragma unroll
            for (int nt = 0; nt < 16; nt++) {
                uint32_t b[2];
                lds64(b, VSb + (uint32_t)(sp * 1024 + nt * 64 + lane * 2) * 4);
                mma_tf32(accE[nt], aE, b);
                mma_tf32(accR[nt], aR, b);
            }
        }
        __syncthreads();
    }

    // ---- epilogue: quad-reduce row sums, normalize, store ----
    zg  += __shfl_xor_sync(0xffffffffu, zg, 1);
    zg  += __shfl_xor_sync(0xffffffffu, zg, 2);
    zg8 += __shfl_xor_sync(0xffffffffu, zg8, 1);
    zg8 += __shfl_xor_sync(0xffffffffu, zg8, 2);
    rg  += __shfl_xor_sync(0xffffffffu, rg, 1);
    rg  += __shfl_xor_sync(0xffffffffu, rg, 2);
    rg8 += __shfl_xor_sync(0xffffffffu, rg8, 1);
    rg8 += __shfl_xor_sync(0xffffffffu, rg8, 2);

    const float iz0 = 1.f / zg;
    const float iz1 = 1.f / zg8;
    const float dn0 = 1.f / fmaf(0.1f, rg, 1.f);
    const float dn1 = 1.f / fmaf(0.1f, rg8, 1.f);

    const int r0 = q0 + w * 16 + g;
    #pragma unroll
    for (int nt = 0; nt < 16; nt++) {
        int col = dh0 + nt * 8 + 2 * q;
        float2 o0, o1;
        o0.x = fmaf(accE[nt][0], iz0, 0.1f * accR[nt][0]) * dn0;
        o0.y = fmaf(accE[nt][1], iz0, 0.1f * accR[nt][1]) * dn0;
        o1.x = fmaf(accE[nt][2], iz1, 0.1f * accR[nt][2]) * dn1;
        o1.y = fmaf(accE[nt][3], iz1, 0.1f * accR[nt][3]) * dn1;
        *(float2*)&out[(size_t)r0 * D_P + col]       = o0;
        *(float2*)&out[(size_t)(r0 + 8) * D_P + col] = o1;
    }
}

// ---------------------------------------------------------------------------
extern "C" void kernel_launch(void* const* d_in, const int* in_sizes, int n_in,
                              void* d_out, int out_size) {
    const float* x  = (const float*)d_in[0];
    const float* y  = (const float*)d_in[1];
    const float* Wq = (const float*)d_in[2];
    const float* Wk = (const float*)d_in[3];
    const float* Wv = (const float*)d_in[4];
    float* out = (float*)d_out;

    cudaFuncSetAttribute(attn_kernel, cudaFuncAttributeMaxDynamicSharedMemorySize,
                         ATT_SMEM);

    proj_kv_kernel<<<(2 * MCTX * D_P + 255) / 256, 256>>>(y, Wk, Wv);
    qgemm_kernel<<<dim3(D_P / 64, N_Q / 64), 256>>>(x, Wq);
    qrepack_kernel<<<(N_Q * D_P / 4) / 256, 256>>>();
    attn_kernel<<<dim3(N_Q / 128, 2), 256, ATT_SMEM>>>(out);
}